// round 10
// baseline (speedup 1.0000x reference)
#include <cuda_runtime.h>

#define B_   256
#define R_   1152
#define C_   10
#define IC_  8
#define OC_  16
#define RT_  16
#define CHUNKS_ (R_/RT_)   /* 72 */
#define NG_   (B_*C_*OC_)  /* 40960 */

// Scratch (static device memory — no allocations).
__device__ __align__(16) float g_Vsum[NG_];             // running sum of v_j
__device__ __align__(16) float g_scratch[CHUNKS_*NG_];  // per-r-chunk partial s

// ---- packed fp32x2 helpers (Blackwell FFMA2 — only reachable via PTX) ------
typedef unsigned long long u64t;
__device__ __forceinline__ u64t fma2(u64t a, u64t b, u64t c) {
    u64t d;
    asm("fma.rn.f32x2 %0, %1, %2, %3;" : "=l"(d) : "l"(a), "l"(b), "l"(c));
    return d;
}
__device__ __forceinline__ u64t mul2(u64t a, u64t b) {
    u64t d;
    asm("mul.rn.f32x2 %0, %1, %2;" : "=l"(d) : "l"(a), "l"(b));
    return d;
}
__device__ __forceinline__ u64t bcast2(float x) {
    u64t d; unsigned int u = __float_as_uint(x);
    asm("mov.b64 %0, {%1, %1};" : "=l"(d) : "r"(u));
    return d;
}
__device__ __forceinline__ float2 unpack2(u64t v) {
    unsigned int lo, hi;
    asm("mov.b64 {%0, %1}, %2;" : "=r"(lo), "=r"(hi) : "l"(v));
    return make_float2(__uint_as_float(lo), __uint_as_float(hi));
}

// Shared W tile layout: Wt[rc][op][i] in float2 units, op-stride padded to 10
// (80 bytes) so the 8 op bank-groups are all distinct (op*20 mod 32 perm).
// rc = r_local*10 + c (0..159). Size = 160*80 float2 = 12800 f2 = 102400 B.
#define WT_F2_   (160*80)
#define SMEM_BYTES_ (WT_F2_*8)

__device__ __forceinline__ void load_w_tile(float2* Wt, const float* w,
                                            int chunk, int tid) {
    const float2* wg = reinterpret_cast<const float2*>(w)
                     + (size_t)chunk * (RT_*C_*IC_*OC_/2);       // 10240 f2/chunk
    #pragma unroll
    for (int j = 0; j < (RT_*C_*IC_*OC_/2)/512; ++j) {           // 20 iters
        int g2 = tid + j*512;                // coalesced global read
        float2 v = wg[g2];
        int op = g2 & 7;                     // o-pair
        int i  = (g2 >> 3) & 7;              // input channel
        int rc = g2 >> 6;                    // r_local*10 + c
        Wt[rc*80 + op*10 + i] = v;           // transposed scatter (bank-safe)
    }
}

// ---------------------------------------------------------------------------
// First routing pass (uniform 0.1): osplit=8, nb=2. Grid (CHUNKS_,2), block 512.
// Thread -> (op = tid&7, batch pair). ~90 regs.
// ---------------------------------------------------------------------------
__global__ __launch_bounds__(512, 1)
void pass_first(const float* __restrict__ x, const float* __restrict__ w) {
    extern __shared__ __align__(16) float2 Wt[];
    const int tid   = threadIdx.x;
    const int chunk = blockIdx.x;
    const int r0    = chunk * RT_;
    const int os    = tid & 7;
    const int b0    = blockIdx.y * 128 + (tid >> 3) * 2;

    load_w_tile(Wt, w, chunk, tid);
    __syncthreads();

    u64t sA[C_], sB[C_];
    #pragma unroll
    for (int c = 0; c < C_; ++c) { sA[c] = 0ull; sB[c] = 0ull; }

    const float* xr0 = x + ((size_t)b0       * R_ + r0) * IC_;
    const float* xr1 = x + ((size_t)(b0 + 1) * R_ + r0) * IC_;

    #pragma unroll 1
    for (int r = 0; r < RT_; ++r) {
        float4 xa = *reinterpret_cast<const float4*>(xr0 + r*IC_);
        float4 xb = *reinterpret_cast<const float4*>(xr0 + r*IC_ + 4);
        float4 ya = *reinterpret_cast<const float4*>(xr1 + r*IC_);
        float4 yb = *reinterpret_cast<const float4*>(xr1 + r*IC_ + 4);
        u64t x2[8], y2[8];
        x2[0]=bcast2(xa.x); x2[1]=bcast2(xa.y); x2[2]=bcast2(xa.z); x2[3]=bcast2(xa.w);
        x2[4]=bcast2(xb.x); x2[5]=bcast2(xb.y); x2[6]=bcast2(xb.z); x2[7]=bcast2(xb.w);
        y2[0]=bcast2(ya.x); y2[1]=bcast2(ya.y); y2[2]=bcast2(ya.z); y2[3]=bcast2(ya.w);
        y2[4]=bcast2(yb.x); y2[5]=bcast2(yb.y); y2[6]=bcast2(yb.z); y2[7]=bcast2(yb.w);

        const float2* wb = Wt + (r*10)*80 + os*10;
        #pragma unroll
        for (int c = 0; c < C_; ++c) {
            const ulonglong2* p = reinterpret_cast<const ulonglong2*>(wb + c*80);
            #pragma unroll
            for (int ii = 0; ii < 4; ++ii) {
                ulonglong2 q = p[ii];                     // LDS.128, conflict-free
                sA[c] = fma2(x2[2*ii],   q.x, sA[c]);
                sA[c] = fma2(x2[2*ii+1], q.y, sA[c]);
                sB[c] = fma2(y2[2*ii],   q.x, sB[c]);
                sB[c] = fma2(y2[2*ii+1], q.y, sB[c]);
            }
        }
    }

    const u64t tenth = bcast2(0.1f);
    u64t* d0 = reinterpret_cast<u64t*>(g_scratch + ((size_t)chunk*B_ +  b0     )*(C_*OC_));
    u64t* d1 = reinterpret_cast<u64t*>(g_scratch + ((size_t)chunk*B_ + (b0 + 1))*(C_*OC_));
    #pragma unroll
    for (int c = 0; c < C_; ++c) {
        d0[c*8 + os] = mul2(sA[c], tenth);
        d1[c*8 + os] = mul2(sB[c], tenth);
    }
}

// ---------------------------------------------------------------------------
// Routing iteration pass: osplit=8, nb=1, Vsum hoisted to registers.
// Grid (CHUNKS_, 4), block 512. Thread -> (op = tid&7, b = by*64 + tid>>3).
// ~120 regs, 4 warps/SMSP.
// ---------------------------------------------------------------------------
__global__ __launch_bounds__(512, 1)
void pass_iter(const float* __restrict__ x, const float* __restrict__ w) {
    extern __shared__ __align__(16) float2 Wt[];
    const int tid   = threadIdx.x;
    const int chunk = blockIdx.x;
    const int r0    = chunk * RT_;
    const int os    = tid & 7;
    const int b     = blockIdx.y * 64 + (tid >> 3);

    load_w_tile(Wt, w, chunk, tid);

    // Hoist Vsum for this (b, o-pair): loaded ONCE, reused for all 16 routes.
    const u64t* vsp = reinterpret_cast<const u64t*>(g_Vsum + b*(C_*OC_));
    u64t vs2[C_];
    #pragma unroll
    for (int c = 0; c < C_; ++c) vs2[c] = vsp[c*8 + os];

    __syncthreads();

    u64t s2[C_];
    #pragma unroll
    for (int c = 0; c < C_; ++c) s2[c] = 0ull;

    const float* xrow = x + ((size_t)b * R_ + r0) * IC_;

    #pragma unroll 1
    for (int r = 0; r < RT_; ++r) {
        float4 xa = *reinterpret_cast<const float4*>(xrow + r*IC_);
        float4 xb = *reinterpret_cast<const float4*>(xrow + r*IC_ + 4);
        u64t x2[8];
        x2[0]=bcast2(xa.x); x2[1]=bcast2(xa.y); x2[2]=bcast2(xa.z); x2[3]=bcast2(xa.w);
        x2[4]=bcast2(xb.x); x2[5]=bcast2(xb.y); x2[6]=bcast2(xb.z); x2[7]=bcast2(xb.w);

        const float2* wb = Wt + (r*10)*80 + os*10;

        u64t u2[C_];
        float t[C_];
        #pragma unroll
        for (int c = 0; c < C_; ++c) {
            const ulonglong2* p = reinterpret_cast<const ulonglong2*>(wb + c*80);
            u64t a = 0ull;
            #pragma unroll
            for (int ii = 0; ii < 4; ++ii) {
                ulonglong2 q = p[ii];                     // LDS.128, conflict-free
                a = fma2(x2[2*ii],   q.x, a);
                a = fma2(x2[2*ii+1], q.y, a);
            }
            u2[c] = a;
            float2 tp = unpack2(mul2(a, vs2[c]));
            t[c] = tp.x + tp.y;                           // partial dot (this o-pair)
        }

        // complete the dot over the 8 o-pair lanes (same b)
        #pragma unroll
        for (int c = 0; c < C_; ++c) {
            t[c] += __shfl_xor_sync(0xffffffffu, t[c], 1);
            t[c] += __shfl_xor_sync(0xffffffffu, t[c], 2);
            t[c] += __shfl_xor_sync(0xffffffffu, t[c], 4);
        }
        float m = t[0];
        #pragma unroll
        for (int c = 1; c < C_; ++c) m = fmaxf(m, t[c]);
        float z = 0.0f;
        #pragma unroll
        for (int c = 0; c < C_; ++c) { t[c] = __expf(t[c] - m); z += t[c]; }
        float inv = __fdividef(1.0f, z);

        #pragma unroll
        for (int c = 0; c < C_; ++c)
            s2[c] = fma2(bcast2(t[c] * inv), u2[c], s2[c]);
    }

    u64t* dst = reinterpret_cast<u64t*>(g_scratch + ((size_t)chunk*B_ + b)*(C_*OC_));
    #pragma unroll
    for (int c = 0; c < C_; ++c) dst[c*8 + os] = s2[c];
}

// ---------------------------------------------------------------------------
// Reduce 72 partials, squash, update Vsum / emit output.
// Block 256 = 32 g-float4 x 8 k-slices, smem combine, 4-lane shfl. Grid 320.
// ---------------------------------------------------------------------------
template<bool FIRSTV, bool LAST>
__global__ __launch_bounds__(256, 4)
void squash_kernel(float* __restrict__ out) {
    const int tid = threadIdx.x;
    const int ks  = tid >> 5;          // 0..7
    const int gl  = tid & 31;          // 0..31
    const int g4  = blockIdx.x * 32 + gl;   // float4 index into [NG_/4]

    const float4* src = reinterpret_cast<const float4*>(g_scratch);
    float4 a = make_float4(0.f, 0.f, 0.f, 0.f);
    #pragma unroll
    for (int k = 0; k < CHUNKS_/8; ++k) {
        float4 tv = src[(size_t)(ks * (CHUNKS_/8) + k) * (NG_/4) + g4];
        a.x += tv.x; a.y += tv.y; a.z += tv.z; a.w += tv.w;
    }

    __shared__ float4 red[8][32];
    red[ks][gl] = a;
    __syncthreads();

    if (tid < 32) {
        float4 s = red[0][tid];
        #pragma unroll
        for (int j = 1; j < 8; ++j) {
            float4 t = red[j][tid];
            s.x += t.x; s.y += t.y; s.z += t.z; s.w += t.w;
        }
        float sq = s.x*s.x + s.y*s.y + s.z*s.z + s.w*s.w;
        sq += __shfl_xor_sync(0xffffffffu, sq, 1);      // 4 float4 lanes = one
        sq += __shfl_xor_sync(0xffffffffu, sq, 2);      // (b,c) 16-vector
        float n = sqrtf(sq);
        float sc = (sq / (1.0f + sq)) / (n + 1e-8f);
        float4 v = make_float4(s.x*sc, s.y*sc, s.z*sc, s.w*sc);
        int g = blockIdx.x * 32 + tid;
        if (LAST) {
            reinterpret_cast<float4*>(out)[g] = v;
        } else if (FIRSTV) {
            reinterpret_cast<float4*>(g_Vsum)[g] = v;
        } else {
            float4 o = reinterpret_cast<float4*>(g_Vsum)[g];
            o.x += v.x; o.y += v.y; o.z += v.z; o.w += v.w;
            reinterpret_cast<float4*>(g_Vsum)[g] = o;
        }
    }
}

extern "C" void kernel_launch(void* const* d_in, const int* in_sizes, int n_in,
                              void* d_out, int out_size) {
    const float* x = (const float*)d_in[0];
    const float* w = (const float*)d_in[1];
    float* out = (float*)d_out;

    cudaFuncSetAttribute(pass_first, cudaFuncAttributeMaxDynamicSharedMemorySize, SMEM_BYTES_);
    cudaFuncSetAttribute(pass_iter,  cudaFuncAttributeMaxDynamicSharedMemorySize, SMEM_BYTES_);

    dim3 gridF(CHUNKS_, 2);   // 128 batches/CTA (nb=2)
    dim3 gridI(CHUNKS_, 4);   // 64 batches/CTA (nb=1)

    pass_first<<<gridF, 512, SMEM_BYTES_>>>(x, w);   // iter 1 (uniform coupling)
    squash_kernel<true,  false><<<320, 256>>>(out);  // v1, Vsum = v1
    pass_iter<<<gridI, 512, SMEM_BYTES_>>>(x, w);    // iter 2
    squash_kernel<false, false><<<320, 256>>>(out);  // v2, Vsum = v1+v2
    pass_iter<<<gridI, 512, SMEM_BYTES_>>>(x, w);    // iter 3
    squash_kernel<false, true ><<<320, 256>>>(out);  // v3 -> output
}